// round 13
// baseline (speedup 1.0000x reference)
#include <cuda_runtime.h>
#include <cuda_fp16.h>
#include <cstdint>

// GraphConvolution: out[b] = adj[b] @ (x[b] @ W) + bias
// B=8, N=2048, F=128.
// Phase 1: 3-term FP16 mma.sync -> f16 hi/lo support planes [n][f].
// Phase 2: 2-term FP16 mma.sync m16n8k16, M=64 tiles, 256 thr / 8 warps,
//          2 CTAs/SM (independent barrier domains), BK=64 double buffer,
//          1 sync/chunk, ks-pipelined ldmatrix fragments, term-major MMAs.

constexpr int BB = 8;
constexpr int NN = 2048;
constexpr int FF = 128;

__device__ __half g_sup_hi[BB * NN * FF];
__device__ __half g_sup_lo[BB * NN * FF];

// ---------------- common helpers ----------------
__device__ __forceinline__ unsigned s2u(const void* p) {
    return (unsigned)__cvta_generic_to_shared(p);
}
__device__ __forceinline__ void cp16(void* dst, const void* src) {
    asm volatile("cp.async.cg.shared.global [%0], [%1], 16;" :: "r"(s2u(dst)), "l"(src));
}
__device__ __forceinline__ void cpcommit() { asm volatile("cp.async.commit_group;"); }
__device__ __forceinline__ void cpwait1()  { asm volatile("cp.async.wait_group 1;"); }
__device__ __forceinline__ void cpwait0()  { asm volatile("cp.async.wait_group 0;"); }

__device__ __forceinline__ void ldsm_x4(unsigned r[4], unsigned a) {
    asm volatile("ldmatrix.sync.aligned.m8n8.x4.shared.b16 {%0,%1,%2,%3}, [%4];"
                 : "=r"(r[0]), "=r"(r[1]), "=r"(r[2]), "=r"(r[3]) : "r"(a));
}
__device__ __forceinline__ void ldsm_x4_t(unsigned r[4], unsigned a) {
    asm volatile("ldmatrix.sync.aligned.m8n8.x4.trans.shared.b16 {%0,%1,%2,%3}, [%4];"
                 : "=r"(r[0]), "=r"(r[1]), "=r"(r[2]), "=r"(r[3]) : "r"(a));
}
__device__ __forceinline__ void mma_f16(float c[4], const unsigned a[4],
                                        unsigned b0, unsigned b1) {
    asm volatile(
        "mma.sync.aligned.m16n8k16.row.col.f32.f16.f16.f32 "
        "{%0,%1,%2,%3}, {%4,%5,%6,%7}, {%8,%9}, {%0,%1,%2,%3};"
        : "+f"(c[0]), "+f"(c[1]), "+f"(c[2]), "+f"(c[3])
        : "r"(a[0]), "r"(a[1]), "r"(a[2]), "r"(a[3]), "r"(b0), "r"(b1));
}
__device__ __forceinline__ void split_h2(float x, float y, __half2& h, __half2& l) {
    h = __floats2half2_rn(x, y);
    float lx = x - __half2float(__low2half(h));
    float ly = y - __half2float(__high2half(h));
    l = __floats2half2_rn(lx, ly);
}
__device__ __forceinline__ unsigned h2u(__half2 h) {
    return *reinterpret_cast<unsigned*>(&h);
}

// ======================================================================
// Phase 1: support = x @ W (3-term f16 mma), stores f16 hi/lo planes
// ======================================================================
constexpr int P1_BM = 128, P1_BK = 32;
constexpr int LDA_S = 36;
constexpr int LDB_S = 136;
constexpr int A_TILE1 = P1_BM * LDA_S;
constexpr int B_TILE1 = P1_BK * LDB_S;
constexpr int STAGE1 = A_TILE1 + B_TILE1;
constexpr int P1_SMEM = 2 * STAGE1 * 4;

__global__ __launch_bounds__(256, 1)
void phase1_kernel(const float* __restrict__ x, const float* __restrict__ w)
{
    extern __shared__ float smem1[];
    float* AsBuf[2] = { smem1,           smem1 + STAGE1 };
    float* BsBuf[2] = { smem1 + A_TILE1, smem1 + STAGE1 + A_TILE1 };

    const int tid = threadIdx.x;
    const int mtile = blockIdx.x;
    const float* A = x + (size_t)mtile * P1_BM * FF;

    const int warp = tid >> 5, lane = tid & 31;
    const int wm = (warp & 1) * 64;
    const int wn = (warp >> 1) * 32;
    const int g = lane >> 2, t = lane & 3;

    float acc[4][4][4];
#pragma unroll
    for (int i = 0; i < 4; i++)
#pragma unroll
        for (int j = 0; j < 4; j++)
#pragma unroll
            for (int k = 0; k < 4; k++) acc[i][j][k] = 0.f;

    auto stage = [&](int kc, int buf) {
#pragma unroll
        for (int i = 0; i < 4; i++) {
            int idx = tid + i * 256;
            int r = idx >> 3, c = idx & 7;
            cp16(AsBuf[buf] + r * LDA_S + c * 4, A + (size_t)r * FF + kc * P1_BK + c * 4);
        }
#pragma unroll
        for (int i = 0; i < 4; i++) {
            int idx = tid + i * 256;
            int r = idx >> 5, c = idx & 31;
            cp16(BsBuf[buf] + r * LDB_S + c * 4, w + (size_t)(kc * P1_BK + r) * FF + c * 4);
        }
        cpcommit();
    };
    stage(0, 0);

    for (int kc = 0; kc < 4; kc++) {
        if (kc + 1 < 4) { stage(kc + 1, (kc + 1) & 1); cpwait1(); }
        else            { cpwait0(); }
        __syncthreads();
        const float* Asc = AsBuf[kc & 1];
        const float* Bsc = BsBuf[kc & 1];
#pragma unroll
        for (int ks = 0; ks < 2; ks++) {
            unsigned ah[4][4], al[4][4], bh[4][2], bl[4][2];
            const float* Ab = Asc + (wm + g) * LDA_S + ks * 16 + 2 * t;
#pragma unroll
            for (int mf = 0; mf < 4; mf++) {
                const float* p = Ab + mf * 16 * LDA_S;
                float2 v00 = *(const float2*)(p);
                float2 v10 = *(const float2*)(p + 8 * LDA_S);
                float2 v01 = *(const float2*)(p + 8);
                float2 v11 = *(const float2*)(p + 8 * LDA_S + 8);
                __half2 h, l;
                split_h2(v00.x, v00.y, h, l); ah[mf][0] = h2u(h); al[mf][0] = h2u(l);
                split_h2(v10.x, v10.y, h, l); ah[mf][1] = h2u(h); al[mf][1] = h2u(l);
                split_h2(v01.x, v01.y, h, l); ah[mf][2] = h2u(h); al[mf][2] = h2u(l);
                split_h2(v11.x, v11.y, h, l); ah[mf][3] = h2u(h); al[mf][3] = h2u(l);
            }
            const float* Bb = Bsc + (ks * 16 + 2 * t) * LDB_S + wn + g;
#pragma unroll
            for (int nf = 0; nf < 4; nf++) {
                float w0 = Bb[nf * 8];
                float w1 = Bb[LDB_S + nf * 8];
                float w2 = Bb[8 * LDB_S + nf * 8];
                float w3 = Bb[9 * LDB_S + nf * 8];
                __half2 h, l;
                split_h2(w0, w1, h, l); bh[nf][0] = h2u(h); bl[nf][0] = h2u(l);
                split_h2(w2, w3, h, l); bh[nf][1] = h2u(h); bl[nf][1] = h2u(l);
            }
#pragma unroll
            for (int mf = 0; mf < 4; mf++)
#pragma unroll
                for (int nf = 0; nf < 4; nf++)
                    mma_f16(acc[mf][nf], al[mf], bh[nf][0], bh[nf][1]);
#pragma unroll
            for (int mf = 0; mf < 4; mf++)
#pragma unroll
                for (int nf = 0; nf < 4; nf++)
                    mma_f16(acc[mf][nf], ah[mf], bl[nf][0], bl[nf][1]);
#pragma unroll
            for (int mf = 0; mf < 4; mf++)
#pragma unroll
                for (int nf = 0; nf < 4; nf++)
                    mma_f16(acc[mf][nf], ah[mf], bh[nf][0], bh[nf][1]);
        }
        __syncthreads();
    }

    const int rowbase = mtile * P1_BM;
#pragma unroll
    for (int mf = 0; mf < 4; mf++) {
        int r0 = rowbase + wm + mf * 16 + g;
#pragma unroll
        for (int nf = 0; nf < 4; nf++) {
            int col = wn + nf * 8 + 2 * t;
            __half2 h, l;
            split_h2(acc[mf][nf][0], acc[mf][nf][1], h, l);
            *(__half2*)(g_sup_hi + (size_t)r0 * FF + col) = h;
            *(__half2*)(g_sup_lo + (size_t)r0 * FF + col) = l;
            split_h2(acc[mf][nf][2], acc[mf][nf][3], h, l);
            *(__half2*)(g_sup_hi + (size_t)(r0 + 8) * FF + col) = h;
            *(__half2*)(g_sup_lo + (size_t)(r0 + 8) * FF + col) = l;
        }
    }
}

// ======================================================================
// Phase 2: out[b] = adj[b] @ support[b] + bias
// M=64 tiles, 256 thr / 8 warps (32x32 warp tiles), 2 CTAs/SM,
// BK=64 double buffer, 1 sync/chunk, ks-pipelined fragments.
// ======================================================================
constexpr int BM2      = 64;
constexpr int BK2      = 64;
constexpr int KCH      = NN / BK2;            // 32 chunks
constexpr int LDA_H    = 72;                  // halves per A row (64 + 8 pad)
constexpr int A_TILE_B = BM2 * LDA_H * 2;     // 9216
constexpr int LDB_B    = 272;                 // bytes per B row (256 + 16 pad)
constexpr int B_PLANE  = BK2 * LDB_B;         // 17408
constexpr int B_STG_B  = 2 * B_PLANE;         // 34816 (hi, lo)
constexpr int OFF_BIAS = 0;
constexpr int OFF_A    = 1024;
constexpr int OFF_B    = OFF_A + 2 * A_TILE_B;          // 19456
constexpr int P2_SMEM  = OFF_B + 2 * B_STG_B;           // 89088  (2 CTAs/SM)

__global__ __launch_bounds__(256, 2)
void phase2_kernel(const float* __restrict__ adj, const float* __restrict__ bias,
                   float* __restrict__ out)
{
    extern __shared__ __align__(16) char smem[];
    const unsigned sA = s2u(smem + OFF_A);
    const unsigned sB = s2u(smem + OFF_B);
    const int tid = threadIdx.x, warp = tid >> 5, lane = tid & 31;
    const int mtile = blockIdx.x, b = blockIdx.y;

    const float* A = adj + ((size_t)b * NN + (size_t)mtile * BM2) * NN;
    const __half* BH = g_sup_hi + (size_t)b * NN * FF;
    const __half* BL = g_sup_lo + (size_t)b * NN * FF;
    float* C = out + ((size_t)b * NN + (size_t)mtile * BM2) * FF;

    if (tid < 128) ((float*)(smem + OFF_BIAS))[tid] = bias[tid];

    // staging roles (256 threads)
    const int ar = tid >> 2, aq = tid & 3;        // A: row 0..63, 16-col quarter
    const int br = tid >> 2, bq = tid & 3;        // B: row 0..63, 64B segment

    // fragment geometry: 8 warps, 32(M) x 32(N) warp tiles over 64x128
    const int g = lane >> 2, t = lane & 3;
    const int wm = (warp & 1) * 32;
    const int wn = (warp >> 1) * 32;
    const unsigned aoff = (unsigned)((wm + (lane & 7) + ((lane >> 3) & 1) * 8) * (LDA_H * 2)
                                     + (lane >> 4) * 16);
    const unsigned boff = (unsigned)(((lane & 7) + ((lane >> 3) & 1) * 8) * LDB_B
                                     + (wn + (lane >> 4) * 8) * 2);

    float acc[2][4][4];
#pragma unroll
    for (int i = 0; i < 2; i++)
#pragma unroll
        for (int j = 0; j < 4; j++)
#pragma unroll
            for (int k = 0; k < 4; k++) acc[i][j][k] = 0.f;

    auto ldgA = [&](int kc, float4 v[4]) {
        const float* p = A + (size_t)ar * NN + kc * BK2 + aq * 16;
#pragma unroll
        for (int i = 0; i < 4; i++) v[i] = *(const float4*)(p + i * 4);
    };
    auto stsA = [&](int kc, const float4 v[4]) {
        uint4 u0, u1;
        u0.x = h2u(__floats2half2_rn(v[0].x, v[0].y));
        u0.y = h2u(__floats2half2_rn(v[0].z, v[0].w));
        u0.z = h2u(__floats2half2_rn(v[1].x, v[1].y));
        u0.w = h2u(__floats2half2_rn(v[1].z, v[1].w));
        u1.x = h2u(__floats2half2_rn(v[2].x, v[2].y));
        u1.y = h2u(__floats2half2_rn(v[2].z, v[2].w));
        u1.z = h2u(__floats2half2_rn(v[3].x, v[3].y));
        u1.w = h2u(__floats2half2_rn(v[3].z, v[3].w));
        char* d = smem + OFF_A + (kc & 1) * A_TILE_B + ar * (LDA_H * 2) + aq * 32;
        *(uint4*)d = u0;
        *(uint4*)(d + 16) = u1;
    };
    auto cpB = [&](int kc) {
        char* dst = smem + OFF_B + (kc & 1) * B_STG_B + br * LDB_B + bq * 64;
        const __half* sh = BH + (size_t)(kc * BK2 + br) * FF + bq * 32;
        const __half* sl = BL + (size_t)(kc * BK2 + br) * FF + bq * 32;
#pragma unroll
        for (int i = 0; i < 4; i++) {
            cp16(dst + i * 16, sh + i * 8);
            cp16(dst + B_PLANE + i * 16, sl + i * 8);
        }
        cpcommit();
    };

    // fragment load for one k-step
    auto ld_frags = [&](int j, int ks, unsigned af[2][4],
                        unsigned bh[2][4], unsigned bl[2][4]) {
        const unsigned aB = sA + j * A_TILE_B;
        const unsigned bB = sB + j * B_STG_B;
        ldsm_x4(af[0], aB + aoff + ks * 32);
        ldsm_x4(af[1], aB + aoff + 16 * (LDA_H * 2) + ks * 32);
        const unsigned bks = bB + boff + ks * 16 * LDB_B;
        ldsm_x4_t(bl[0], bks + B_PLANE);
        ldsm_x4_t(bl[1], bks + B_PLANE + 32);
        ldsm_x4_t(bh[0], bks);
        ldsm_x4_t(bh[1], bks + 32);
    };
    auto mma_ks = [&](const unsigned af[2][4], const unsigned bh[2][4],
                      const unsigned bl[2][4]) {
        // term-major: all lo-MMAs then all hi-MMAs (acc reuse distance 8)
#pragma unroll
        for (int mf = 0; mf < 2; mf++)
#pragma unroll
            for (int np = 0; np < 2; np++)
#pragma unroll
                for (int p = 0; p < 2; p++)
                    mma_f16(acc[mf][np * 2 + p], af[mf],
                            bl[np][p * 2], bl[np][p * 2 + 1]);
#pragma unroll
        for (int mf = 0; mf < 2; mf++)
#pragma unroll
            for (int np = 0; np < 2; np++)
#pragma unroll
                for (int p = 0; p < 2; p++)
                    mma_f16(acc[mf][np * 2 + p], af[mf],
                            bh[np][p * 2], bh[np][p * 2 + 1]);
    };

    // prologue: stage chunk 0
    {
        float4 v[4];
        ldgA(0, v); stsA(0, v); cpB(0);
    }

    for (int kc = 0; kc < KCH; kc++) {
        float4 v[4];
        const bool pre = (kc + 1 < KCH);
        if (pre) ldgA(kc + 1, v);                // overlap LDG with wait
        cpwait0();
        __syncthreads();                          // chunk kc ready; prior reads done
        if (pre) {
            stsA(kc + 1, v);                      // write other buffer
            cpB(kc + 1);
        }
        // ks-pipelined MMA over chunk kc
        unsigned af[2][2][4], bh[2][2][4], bl[2][2][4];
        const int j = kc & 1;
        ld_frags(j, 0, af[0], bh[0], bl[0]);
#pragma unroll
        for (int ks = 0; ks < 4; ks++) {
            const int cur = ks & 1, nxt = cur ^ 1;
            if (ks < 3) ld_frags(j, ks + 1, af[nxt], bh[nxt], bl[nxt]);
            mma_ks(af[cur], bh[cur], bl[cur]);
        }
    }

    // epilogue
    const float* bsm = (const float*)(smem + OFF_BIAS);
#pragma unroll
    for (int mf = 0; mf < 2; mf++) {
        int r0 = wm + mf * 16 + g;
#pragma unroll
        for (int nf = 0; nf < 4; nf++) {
            int col = wn + nf * 8 + 2 * t;
            float2 bz = *reinterpret_cast<const float2*>(bsm + col);
            float2 u0 = make_float2(acc[mf][nf][0] + bz.x, acc[mf][nf][1] + bz.y);
            float2 u1 = make_float2(acc[mf][nf][2] + bz.x, acc[mf][nf][3] + bz.y);
            *reinterpret_cast<float2*>(C + (size_t)r0       * FF + col) = u0;
            *reinterpret_cast<float2*>(C + (size_t)(r0 + 8) * FF + col) = u1;
        }
    }
}

// ======================================================================
extern "C" void kernel_launch(void* const* d_in, const int* in_sizes, int n_in,
                              void* d_out, int out_size) {
    const float* x    = (const float*)d_in[0];   // [8, 2048, 128]
    const float* adj  = (const float*)d_in[1];   // [8, 2048, 2048]
    const float* w    = (const float*)d_in[2];   // [128, 128]
    const float* bias = (const float*)d_in[3];   // [128]
    float* out = (float*)d_out;                  // [8, 2048, 128]

    cudaFuncSetAttribute(phase1_kernel, cudaFuncAttributeMaxDynamicSharedMemorySize, P1_SMEM);
    cudaFuncSetAttribute(phase2_kernel, cudaFuncAttributeMaxDynamicSharedMemorySize, P2_SMEM);

    phase1_kernel<<<(BB * NN) / P1_BM, 256, P1_SMEM>>>(x, w);
    phase2_kernel<<<dim3(NN / BM2, BB), 256, P2_SMEM>>>(adj, bias, out);
}

// round 14
// speedup vs baseline: 1.2019x; 1.2019x over previous
#include <cuda_runtime.h>
#include <cuda_fp16.h>
#include <cstdint>

// GraphConvolution: out[b] = adj[b] @ (x[b] @ W) + bias
// B=8, N=2048, F=128.
// Phase 1: 3-term FP16 mma.sync, 256 CTAs x 64 rows, single K=128 chunk,
//          stores f16 hi/lo support planes [row][f].
// Phase 2: round-5 proven optimum (63.7us): 2-term FP16 mma.sync m16n8k16,
//          512 thr / 16 warps / 32x32 warp tiles, BK=32, triple buffer,
//          1 sync/chunk, ldmatrix fragments.

constexpr int BB = 8;
constexpr int NN = 2048;
constexpr int FF = 128;

__device__ __half g_sup_hi[BB * NN * FF];
__device__ __half g_sup_lo[BB * NN * FF];

// ---------------- common helpers ----------------
__device__ __forceinline__ unsigned s2u(const void* p) {
    return (unsigned)__cvta_generic_to_shared(p);
}
__device__ __forceinline__ void cp16(void* dst, const void* src) {
    asm volatile("cp.async.cg.shared.global [%0], [%1], 16;" :: "r"(s2u(dst)), "l"(src));
}
__device__ __forceinline__ void cpcommit() { asm volatile("cp.async.commit_group;"); }
__device__ __forceinline__ void cpwait1()  { asm volatile("cp.async.wait_group 1;"); }
__device__ __forceinline__ void cpwait0()  { asm volatile("cp.async.wait_group 0;"); }

__device__ __forceinline__ void ldsm_x4(unsigned r[4], unsigned a) {
    asm volatile("ldmatrix.sync.aligned.m8n8.x4.shared.b16 {%0,%1,%2,%3}, [%4];"
                 : "=r"(r[0]), "=r"(r[1]), "=r"(r[2]), "=r"(r[3]) : "r"(a));
}
__device__ __forceinline__ void ldsm_x4_t(unsigned r[4], unsigned a) {
    asm volatile("ldmatrix.sync.aligned.m8n8.x4.trans.shared.b16 {%0,%1,%2,%3}, [%4];"
                 : "=r"(r[0]), "=r"(r[1]), "=r"(r[2]), "=r"(r[3]) : "r"(a));
}
__device__ __forceinline__ void mma_f16(float c[4], const unsigned a[4],
                                        unsigned b0, unsigned b1) {
    asm volatile(
        "mma.sync.aligned.m16n8k16.row.col.f32.f16.f16.f32 "
        "{%0,%1,%2,%3}, {%4,%5,%6,%7}, {%8,%9}, {%0,%1,%2,%3};"
        : "+f"(c[0]), "+f"(c[1]), "+f"(c[2]), "+f"(c[3])
        : "r"(a[0]), "r"(a[1]), "r"(a[2]), "r"(a[3]), "r"(b0), "r"(b1));
}
__device__ __forceinline__ void split_h2(float x, float y, __half2& h, __half2& l) {
    h = __floats2half2_rn(x, y);
    float lx = x - __half2float(__low2half(h));
    float ly = y - __half2float(__high2half(h));
    l = __floats2half2_rn(lx, ly);
}
__device__ __forceinline__ unsigned h2u(__half2 h) {
    return *reinterpret_cast<unsigned*>(&h);
}

// ======================================================================
// Phase 1: support = x @ W (3-term f16 mma), 64 rows/CTA, single chunk
// ======================================================================
constexpr int P1_BM  = 64;
constexpr int LDA_S  = 132;                  // x smem stride (floats), 132 % 32 == 4
constexpr int LDB_S  = 136;                  // W smem stride (floats), 136 % 32 == 8
constexpr int X_TILE = P1_BM * LDA_S;        // 8448 floats
constexpr int W_TILE = FF * LDB_S;           // 17408 floats
constexpr int P1_SMEM = (X_TILE + W_TILE) * 4;   // 103424 B

__global__ __launch_bounds__(256, 1)
void phase1_kernel(const float* __restrict__ x, const float* __restrict__ w)
{
    extern __shared__ float smem1[];
    float* Xs = smem1;
    float* Ws = smem1 + X_TILE;

    const int tid = threadIdx.x;
    const int mtile = blockIdx.x;            // 256 tiles over 16384 rows
    const float* A = x + (size_t)mtile * P1_BM * FF;

    const int warp = tid >> 5, lane = tid & 31;
    const int wm = (warp & 1) * 32;          // 2 warps along M (32 rows each)
    const int wn = (warp >> 1) * 32;         // 4 warps along N (32 cols each)
    const int g = lane >> 2, t = lane & 3;

    // stage x tile: 64 rows x 32 float4
#pragma unroll
    for (int i = 0; i < 8; i++) {
        int idx = tid + i * 256;
        int r = idx >> 5, c = idx & 31;
        cp16(Xs + r * LDA_S + c * 4, A + (size_t)r * FF + c * 4);
    }
    // stage W: 128 rows x 32 float4
#pragma unroll
    for (int i = 0; i < 16; i++) {
        int idx = tid + i * 256;
        int r = idx >> 5, c = idx & 31;
        cp16(Ws + r * LDB_S + c * 4, w + (size_t)r * FF + c * 4);
    }
    cpcommit();
    cpwait0();
    __syncthreads();

    float acc[2][4][4];
#pragma unroll
    for (int i = 0; i < 2; i++)
#pragma unroll
        for (int j = 0; j < 4; j++)
#pragma unroll
            for (int k = 0; k < 4; k++) acc[i][j][k] = 0.f;

#pragma unroll
    for (int ks = 0; ks < 8; ks++) {          // K = 128, 16 per step
        unsigned ah[2][4], al[2][4], bh[4][2], bl[4][2];
        const float* Ab = Xs + (wm + g) * LDA_S + ks * 16 + 2 * t;
#pragma unroll
        for (int mf = 0; mf < 2; mf++) {
            const float* p = Ab + mf * 16 * LDA_S;
            float2 v00 = *(const float2*)(p);
            float2 v10 = *(const float2*)(p + 8 * LDA_S);
            float2 v01 = *(const float2*)(p + 8);
            float2 v11 = *(const float2*)(p + 8 * LDA_S + 8);
            __half2 h, l;
            split_h2(v00.x, v00.y, h, l); ah[mf][0] = h2u(h); al[mf][0] = h2u(l);
            split_h2(v10.x, v10.y, h, l); ah[mf][1] = h2u(h); al[mf][1] = h2u(l);
            split_h2(v01.x, v01.y, h, l); ah[mf][2] = h2u(h); al[mf][2] = h2u(l);
            split_h2(v11.x, v11.y, h, l); ah[mf][3] = h2u(h); al[mf][3] = h2u(l);
        }
        const float* Bb = Ws + (ks * 16 + 2 * t) * LDB_S + wn + g;
#pragma unroll
        for (int nf = 0; nf < 4; nf++) {
            float w0 = Bb[nf * 8];
            float w1 = Bb[LDB_S + nf * 8];
            float w2 = Bb[8 * LDB_S + nf * 8];
            float w3 = Bb[9 * LDB_S + nf * 8];
            __half2 h, l;
            split_h2(w0, w1, h, l); bh[nf][0] = h2u(h); bl[nf][0] = h2u(l);
            split_h2(w2, w3, h, l); bh[nf][1] = h2u(h); bl[nf][1] = h2u(l);
        }
#pragma unroll
        for (int mf = 0; mf < 2; mf++)
#pragma unroll
            for (int nf = 0; nf < 4; nf++)
                mma_f16(acc[mf][nf], al[mf], bh[nf][0], bh[nf][1]);
#pragma unroll
        for (int mf = 0; mf < 2; mf++)
#pragma unroll
            for (int nf = 0; nf < 4; nf++)
                mma_f16(acc[mf][nf], ah[mf], bl[nf][0], bl[nf][1]);
#pragma unroll
        for (int mf = 0; mf < 2; mf++)
#pragma unroll
            for (int nf = 0; nf < 4; nf++)
                mma_f16(acc[mf][nf], ah[mf], bh[nf][0], bh[nf][1]);
    }

    // store hi/lo f16 planes, [row][f]
    const int rowbase = mtile * P1_BM;
#pragma unroll
    for (int mf = 0; mf < 2; mf++) {
        int r0 = rowbase + wm + mf * 16 + g;
#pragma unroll
        for (int nf = 0; nf < 4; nf++) {
            int col = wn + nf * 8 + 2 * t;
            __half2 h, l;
            split_h2(acc[mf][nf][0], acc[mf][nf][1], h, l);
            *(__half2*)(g_sup_hi + (size_t)r0 * FF + col) = h;
            *(__half2*)(g_sup_lo + (size_t)r0 * FF + col) = l;
            split_h2(acc[mf][nf][2], acc[mf][nf][3], h, l);
            *(__half2*)(g_sup_hi + (size_t)(r0 + 8) * FF + col) = h;
            *(__half2*)(g_sup_lo + (size_t)(r0 + 8) * FF + col) = l;
        }
    }
}

// ======================================================================
// Phase 2 (round-5 proven optimum): out[b] = adj[b] @ support[b] + bias
// 512 thr / 16 warps / 32x32 warp tiles / BK=32 / triple buffer / 1 sync
// ======================================================================
constexpr int LDA_H    = 40;                 // halves per A row (32 + 8 pad)
constexpr int A_TILE_B = 128 * LDA_H * 2;    // 10240
constexpr int LDB_B    = 272;                // bytes per B row (256 + 16 pad)
constexpr int B_PLANE  = 32 * LDB_B;         // 8704
constexpr int B_STG_B  = 2 * B_PLANE;        // 17408 (hi, lo)
constexpr int OFF_BIAS = 0;
constexpr int OFF_A    = 1024;
constexpr int OFF_B    = OFF_A + 3 * A_TILE_B;        // 31744
constexpr int P2_SMEM  = OFF_B + 3 * B_STG_B;         // 83968

__global__ __launch_bounds__(512, 1)
void phase2_kernel(const float* __restrict__ adj, const float* __restrict__ bias,
                   float* __restrict__ out)
{
    extern __shared__ __align__(16) char smem[];
    const unsigned sA = s2u(smem + OFF_A);
    const unsigned sB = s2u(smem + OFF_B);
    const int tid = threadIdx.x, warp = tid >> 5, lane = tid & 31;
    const int mtile = blockIdx.x, b = blockIdx.y;

    const float* A = adj + ((size_t)b * NN + (size_t)mtile * 128) * NN;
    const __half* BH = g_sup_hi + (size_t)b * NN * FF;
    const __half* BL = g_sup_lo + (size_t)b * NN * FF;
    float* C = out + ((size_t)b * NN + (size_t)mtile * 128) * FF;

    if (tid < 128) ((float*)(smem + OFF_BIAS))[tid] = bias[tid];

    // staging roles (512 threads)
    const int ar = tid >> 2, aq = tid & 3;        // A: row 0..127, 8-float quarter
    const int br = tid >> 4, bs = tid & 15;       // B: row 0..31, 16B segment

    // fragment geometry: 16 warps, 32(M) x 32(N) tiles
    const int g = lane >> 2, t = lane & 3;
    const int wm = (warp & 3) * 32;
    const int wn = (warp >> 2) * 32;
    const unsigned aoff = (unsigned)((wm + (lane & 7) + ((lane >> 3) & 1) * 8) * (LDA_H * 2)
                                     + (lane >> 4) * 16);
    const unsigned boff = (unsigned)(((lane & 7) + ((lane >> 3) & 1) * 8) * LDB_B
                                     + (wn + (lane >> 4) * 8) * 2);

    float acc[2][4][4];
#pragma unroll
    for (int i = 0; i < 2; i++)
#pragma unroll
        for (int j = 0; j < 4; j++)
#pragma unroll
            for (int k = 0; k < 4; k++) acc[i][j][k] = 0.f;

    auto ldgA = [&](int kc, float4& v0, float4& v1) {
        const float* p = A + (size_t)ar * NN + kc * 32 + aq * 8;
        v0 = *(const float4*)p;
        v1 = *(const float4*)(p + 4);
    };
    auto stsA = [&](int kc, float4 v0, float4 v1) {
        __half2 p0 = __floats2half2_rn(v0.x, v0.y);
        __half2 p1 = __floats2half2_rn(v0.z, v0.w);
        __half2 p2 = __floats2half2_rn(v1.x, v1.y);
        __half2 p3 = __floats2half2_rn(v1.z, v1.w);
        uint4 u;
        u.x = *(unsigned*)&p0; u.y = *(unsigned*)&p1;
        u.z = *(unsigned*)&p2; u.w = *(unsigned*)&p3;
        *(uint4*)(smem + OFF_A + (kc % 3) * A_TILE_B + ar * (LDA_H * 2) + aq * 16) = u;
    };
    auto cpB = [&](int kc) {
        char* dst = smem + OFF_B + (kc % 3) * B_STG_B + br * LDB_B + bs * 16;
        const __half* sh = BH + (size_t)(kc * 32 + br) * FF + bs * 8;
        const __half* sl = BL + (size_t)(kc * 32 + br) * FF + bs * 8;
        cp16(dst, sh);
        cp16(dst + B_PLANE, sl);
        cpcommit();
    };

    auto mma_chunk = [&](int j) {
        const unsigned aB = sA + j * A_TILE_B;
        const unsigned bB = sB + j * B_STG_B;
#pragma unroll
        for (int ks = 0; ks < 2; ks++) {
            unsigned af[2][4];
            ldsm_x4(af[0], aB + aoff + ks * 32);
            ldsm_x4(af[1], aB + aoff + 16 * (LDA_H * 2) + ks * 32);
            unsigned bh[2][4], bl[2][4];
            const unsigned bks = bB + boff + ks * 16 * LDB_B;
            ldsm_x4_t(bh[0], bks);
            ldsm_x4_t(bh[1], bks + 32);
            ldsm_x4_t(bl[0], bks + B_PLANE);
            ldsm_x4_t(bl[1], bks + B_PLANE + 32);
#pragma unroll
            for (int mf = 0; mf < 2; mf++)
#pragma unroll
                for (int np = 0; np < 2; np++)
#pragma unroll
                    for (int p = 0; p < 2; p++) {
                        float* c = acc[mf][np * 2 + p];
                        mma_f16(c, af[mf], bl[np][p * 2], bl[np][p * 2 + 1]);
                        mma_f16(c, af[mf], bh[np][p * 2], bh[np][p * 2 + 1]);
                    }
        }
    };

    // prologue: chunks 0 and 1
    {
        float4 v0, v1;
        ldgA(0, v0, v1); stsA(0, v0, v1); cpB(0);
        ldgA(1, v0, v1); stsA(1, v0, v1); cpB(1);
    }

    for (int kc = 0; kc < 64; kc++) {
        float4 v0, v1;
        const bool pre = (kc + 2 < 64);
        if (pre) ldgA(kc + 2, v0, v1);           // overlap LDG with wait+MMA
        if (kc < 63) cpwait1(); else cpwait0();
        __syncthreads();
        mma_chunk(kc % 3);
        if (pre) {
            stsA(kc + 2, v0, v1);
            cpB(kc + 2);
        }
    }

    // epilogue
    const float* bsm = (const float*)(smem + OFF_BIAS);
#pragma unroll
    for (int mf = 0; mf < 2; mf++) {
        int r0 = wm + mf * 16 + g;
#pragma unroll
        for (int nf = 0; nf < 4; nf++) {
            int col = wn + nf * 8 + 2 * t;
            float2 bz = *reinterpret_cast<const float2*>(bsm + col);
            float2 u0 = make_float2(acc[mf][nf][0] + bz.x, acc[mf][nf][1] + bz.y);
            float2 u1 = make_float2(acc[mf][nf][2] + bz.x, acc[mf][nf][3] + bz.y);
            *reinterpret_cast<float2*>(C + (size_t)r0       * FF + col) = u0;
            *reinterpret_cast<float2*>(C + (size_t)(r0 + 8) * FF + col) = u1;
        }
    }
}

// ======================================================================
extern "C" void kernel_launch(void* const* d_in, const int* in_sizes, int n_in,
                              void* d_out, int out_size) {
    const float* x    = (const float*)d_in[0];   // [8, 2048, 128]
    const float* adj  = (const float*)d_in[1];   // [8, 2048, 2048]
    const float* w    = (const float*)d_in[2];   // [128, 128]
    const float* bias = (const float*)d_in[3];   // [128]
    float* out = (float*)d_out;                  // [8, 2048, 128]

    cudaFuncSetAttribute(phase1_kernel, cudaFuncAttributeMaxDynamicSharedMemorySize, P1_SMEM);
    cudaFuncSetAttribute(phase2_kernel, cudaFuncAttributeMaxDynamicSharedMemorySize, P2_SMEM);

    phase1_kernel<<<(BB * NN) / P1_BM, 256, P1_SMEM>>>(x, w);
    phase2_kernel<<<dim3(NN / 128, BB), 512, P2_SMEM>>>(adj, bias, out);
}